// round 1
// baseline (speedup 1.0000x reference)
#include <cuda_runtime.h>
#include <cuda_bf16.h>

// SlideMean_Norm: out = x - sliding_window_mean(x, win=300, clamped) along T
// x: [32, 1, 16000, 80] float32
//
// window for index t: [max(t-150,0), min(t+150, T-1))  (end exclusive)
// count = end - start (== 300 for 150 <= t <= 15849)

namespace {
constexpr int T     = 16000;
constexpr int F     = 80;
constexpr int HALF  = 150;
constexpr int CHUNK = 500;                 // 16000 / 500 = 32 chunks
constexpr int NCHUNK = T / CHUNK;          // 32
constexpr float INV_FULL = 1.0f / 300.0f;
}

// Interior chunks: no clamping, count == 300 everywhere.
// One thread per feature column; sequential slide over CHUNK time steps.
__global__ __launch_bounds__(F) void slide_interior_kernel(
    const float* __restrict__ x, float* __restrict__ out)
{
    const int f  = threadIdx.x;                       // 0..79
    const int b  = blockIdx.y;                        // 0..31
    const int t0 = (blockIdx.x + 1) * CHUNK;          // chunks 1..30

    const float* __restrict__ xb = x   + (size_t)b * T * F + f;
    float*       __restrict__ ob = out + (size_t)b * T * F + f;

    // Prologue: ws = sum x[t0-150 .. t0+149]  (300 elems), 4-way ILP
    const int base = t0 - HALF;
    float s0 = 0.f, s1 = 0.f, s2 = 0.f, s3 = 0.f;
    #pragma unroll 4
    for (int k = 0; k < 2 * HALF; k += 4) {
        s0 += xb[(base + k + 0) * F];
        s1 += xb[(base + k + 1) * F];
        s2 += xb[(base + k + 2) * F];
        s3 += xb[(base + k + 3) * F];
    }
    float ws = (s0 + s1) + (s2 + s3);

    const float* __restrict__ cur   = xb + t0 * F;
    const float* __restrict__ lead  = xb + (t0 + HALF) * F;
    const float* __restrict__ trail = xb + (t0 - HALF) * F;
    float*       __restrict__ o     = ob + t0 * F;

    #pragma unroll 4
    for (int i = 0; i < CHUNK; ++i) {
        float xv = cur[i * F];
        o[i * F] = xv - ws * INV_FULL;
        ws += lead[i * F] - trail[i * F];
    }
}

// Edge chunks (first and last): general clamped path with per-step count.
__global__ __launch_bounds__(F) void slide_edge_kernel(
    const float* __restrict__ x, float* __restrict__ out)
{
    const int f  = threadIdx.x;
    const int b  = blockIdx.y;
    const int t0 = (blockIdx.x == 0) ? 0 : (T - CHUNK);

    const float* __restrict__ xb = x   + (size_t)b * T * F + f;
    float*       __restrict__ ob = out + (size_t)b * T * F + f;

    int s = t0 - HALF; if (s < 0) s = 0;
    int e = t0 + HALF; if (e > T - 1) e = T - 1;

    // Initial window sum over [s, e)
    float ws = 0.f;
    {
        float a0 = 0.f, a1 = 0.f;
        int k = s;
        for (; k + 1 < e; k += 2) {
            a0 += xb[(k + 0) * F];
            a1 += xb[(k + 1) * F];
        }
        if (k < e) a0 += xb[k * F];
        ws = a0 + a1;
    }

    for (int t = t0; t < t0 + CHUNK; ++t) {
        int cnt = e - s;
        float inv = (cnt == 2 * HALF) ? INV_FULL : (1.0f / (float)cnt);
        float xv = xb[t * F];
        ob[t * F] = xv - ws * inv;

        int sn = t + 1 - HALF; if (sn < 0) sn = 0;
        int en = t + 1 + HALF; if (en > T - 1) en = T - 1;
        if (en > e) ws += xb[e * F];
        if (sn > s) ws -= xb[s * F];
        s = sn; e = en;
    }
}

extern "C" void kernel_launch(void* const* d_in, const int* in_sizes, int n_in,
                              void* d_out, int out_size)
{
    const float* x = (const float*)d_in[0];
    float* out = (float*)d_out;

    dim3 blk(F);
    dim3 grid_int(NCHUNK - 2, 32);   // interior chunks 1..30
    dim3 grid_edge(2, 32);           // chunks 0 and 31

    slide_interior_kernel<<<grid_int, blk>>>(x, out);
    slide_edge_kernel<<<grid_edge, blk>>>(x, out);
}

// round 2
// speedup vs baseline: 1.6200x; 1.6200x over previous
#include <cuda_runtime.h>
#include <cuda_bf16.h>

// SlideMean_Norm: out = x - clamped_sliding_mean(x, win=300) along T
// x: [32, 1, 16000, 80] float32
// window for t: [max(t-150,0), min(t+150, T-1)), count = e - s

namespace {
constexpr int T      = 16000;
constexpr int F4     = 20;        // 80 floats = 20 float4 per row
constexpr int HALF   = 150;
constexpr int C      = 125;       // chunk length (time steps per thread)
constexpr int NCHUNK = T / C;     // 128
constexpr int CPB    = 8;         // chunks per block -> 160 threads = 5 warps
constexpr float INV_FULL = 1.0f / 300.0f;
}

__device__ __forceinline__ float4 f4_add(float4 a, float4 b) {
    return make_float4(a.x + b.x, a.y + b.y, a.z + b.z, a.w + b.w);
}
__device__ __forceinline__ float4 f4_sub(float4 a, float4 b) {
    return make_float4(a.x - b.x, a.y - b.y, a.z - b.z, a.w - b.w);
}
__device__ __forceinline__ float4 f4_fnms(float4 x, float4 ws, float inv) {
    // x - ws*inv
    return make_float4(fmaf(-ws.x, inv, x.x), fmaf(-ws.y, inv, x.y),
                       fmaf(-ws.z, inv, x.z), fmaf(-ws.w, inv, x.w));
}

__global__ __launch_bounds__(F4 * CPB) void slide_kernel(
    const float4* __restrict__ x, float4* __restrict__ out)
{
    const int lane  = threadIdx.x;                       // 0..19 (f4 column)
    const int chunk = blockIdx.x * CPB + threadIdx.y;    // 0..127
    const int b     = blockIdx.y;                        // 0..31
    const int t0    = chunk * C;

    const float4* __restrict__ xb = x   + (size_t)b * T * F4 + lane;
    float4*       __restrict__ ob = out + (size_t)b * T * F4 + lane;

    const bool edge = (chunk < 2) | (chunk >= NCHUNK - 2);

    if (!edge) {
        // ---- Interior: count == 300 everywhere, no clamping ----
        // Prologue: ws = sum of rows [t0-150, t0+150)
        const int base = t0 - HALF;
        float4 a0 = make_float4(0.f, 0.f, 0.f, 0.f);
        float4 a1 = make_float4(0.f, 0.f, 0.f, 0.f);
        #pragma unroll 5
        for (int k = 0; k < 2 * HALF; k += 2) {
            a0 = f4_add(a0, xb[(size_t)(base + k) * F4]);
            a1 = f4_add(a1, xb[(size_t)(base + k + 1) * F4]);
        }
        float4 ws = f4_add(a0, a1);

        const float4* __restrict__ cur   = xb + (size_t)t0 * F4;
        const float4* __restrict__ lead  = xb + (size_t)(t0 + HALF) * F4;
        const float4* __restrict__ trail = xb + (size_t)(t0 - HALF) * F4;
        float4*       __restrict__ o     = ob + (size_t)t0 * F4;

        #pragma unroll 5
        for (int i = 0; i < C; ++i) {
            float4 xv = cur[(size_t)i * F4];
            o[(size_t)i * F4] = f4_fnms(xv, ws, INV_FULL);
            ws = f4_add(ws, f4_sub(lead[(size_t)i * F4], trail[(size_t)i * F4]));
        }
    } else {
        // ---- Edge: general clamped path ----
        int s = t0 - HALF; if (s < 0) s = 0;
        int e = t0 + HALF; if (e > T - 1) e = T - 1;

        float4 a0 = make_float4(0.f, 0.f, 0.f, 0.f);
        float4 a1 = make_float4(0.f, 0.f, 0.f, 0.f);
        int k = s;
        for (; k + 1 < e; k += 2) {
            a0 = f4_add(a0, xb[(size_t)k * F4]);
            a1 = f4_add(a1, xb[(size_t)(k + 1) * F4]);
        }
        if (k < e) a0 = f4_add(a0, xb[(size_t)k * F4]);
        float4 ws = f4_add(a0, a1);

        for (int t = t0; t < t0 + C; ++t) {
            int cnt = e - s;
            float inv = (cnt == 2 * HALF) ? INV_FULL : (1.0f / (float)cnt);
            float4 xv = xb[(size_t)t * F4];
            ob[(size_t)t * F4] = f4_fnms(xv, ws, inv);

            int sn = t + 1 - HALF; if (sn < 0) sn = 0;
            int en = t + 1 + HALF; if (en > T - 1) en = T - 1;
            if (en > e) ws = f4_add(ws, xb[(size_t)e * F4]);
            if (sn > s) ws = f4_sub(ws, xb[(size_t)s * F4]);
            s = sn; e = en;
        }
    }
}

extern "C" void kernel_launch(void* const* d_in, const int* in_sizes, int n_in,
                              void* d_out, int out_size)
{
    const float4* x = (const float4*)d_in[0];
    float4* out = (float4*)d_out;

    dim3 blk(F4, CPB);                  // 160 threads = 5 warps
    dim3 grid(NCHUNK / CPB, 32);        // 16 x 32 = 512 blocks
    slide_kernel<<<grid, blk>>>(x, out);
}

// round 3
// speedup vs baseline: 3.0321x; 1.8717x over previous
#include <cuda_runtime.h>

// SlideMean_Norm: out = x - clamped_sliding_mean(x, win=300) along T
// x: [32, 1, 16000, 80] float32
// window for t: [max(t-150,0), min(t+150, T-1)), count = e - s
//
// Strategy: smem-tiled. Block = (time-chunk of 1000 rows, batch, feature-half).
// Stage 1300 half-rows (with 150-row halo each side, zero-padded) into smem,
// build 25-row span sums, init each 25-row subchunk's window from 12 spans,
// then slide entirely out of smem. GMEM traffic = 1.3x read + 1x write.

namespace {
constexpr int T     = 16000;
constexpr int F4    = 20;          // 80 floats = 20 float4 per full row
constexpr int HALF  = 150;
constexpr int CB    = 1000;        // output rows per block
constexpr int NCH   = T / CB;      // 16
constexpr int SUB   = 25;          // rows per thread subchunk
constexpr int NSUB  = CB / SUB;    // 40
constexpr int ROWS  = CB + 2*HALF; // 1300 staged rows
constexpr int NSPAN = ROWS / SUB;  // 52
constexpr int WSPAN = 2*HALF/SUB;  // 12 spans per window
constexpr int LN    = 10;          // float4 lanes per half-row (160 B)
constexpr int NTHR  = LN * NSUB;   // 400 threads
constexpr float INV_FULL = 1.0f / 300.0f;
constexpr int SMEM_BYTES = (ROWS*LN + NSPAN*LN) * (int)sizeof(float4);
}

__device__ __forceinline__ float4 operator+(float4 a, float4 b) {
    return make_float4(a.x+b.x, a.y+b.y, a.z+b.z, a.w+b.w);
}
__device__ __forceinline__ float4 operator-(float4 a, float4 b) {
    return make_float4(a.x-b.x, a.y-b.y, a.z-b.z, a.w-b.w);
}
__device__ __forceinline__ void operator+=(float4& a, float4 b) { a = a + b; }
__device__ __forceinline__ void operator-=(float4& a, float4 b) { a = a - b; }
__device__ __forceinline__ float4 f4_fnms(float4 x, float4 ws, float inv) {
    return make_float4(fmaf(-ws.x, inv, x.x), fmaf(-ws.y, inv, x.y),
                       fmaf(-ws.z, inv, x.z), fmaf(-ws.w, inv, x.w));
}

__global__ __launch_bounds__(NTHR, 1) void slide_smem_kernel(
    const float4* __restrict__ x, float4* __restrict__ out)
{
    extern __shared__ float4 smem[];
    float4* __restrict__ tile = smem;              // [ROWS][LN]
    float4* __restrict__ span = smem + ROWS * LN;  // [NSPAN][LN]

    const int ln   = threadIdx.x;                  // 0..9
    const int ty   = threadIdx.y;                  // 0..39
    const int tid  = ty * LN + ln;
    const int cx   = blockIdx.x;                   // chunk 0..15
    const int b    = blockIdx.y;                   // 0..31
    const int hoff = blockIdx.z * LN;              // feature-half offset (f4)
    const int t0   = cx * CB;
    const int gbase = t0 - HALF;

    const float4 zero = make_float4(0.f, 0.f, 0.f, 0.f);

    // ---- Stage 1300 half-rows into smem (zero-pad outside [0,T)) ----
    {
        const int r0 = tid / LN;   // == ty
        const float4* __restrict__ src =
            x + ((size_t)b * T + gbase) * F4 + hoff + ln;
        #pragma unroll
        for (int r = r0; r < ROWS; r += NSUB) {
            const int g = gbase + r;
            float4 v = zero;
            if (g >= 0 && g < T) v = src[(size_t)r * F4];
            tile[r * LN + ln] = v;
        }
    }
    __syncthreads();

    // ---- Span sums: 52 spans of 25 rows each ----
    {
        #pragma unroll
        for (int j = ty; j < NSPAN; j += NSUB) {
            float4 s0 = zero, s1 = zero;
            const float4* __restrict__ tp = tile + (j * SUB) * LN + ln;
            #pragma unroll
            for (int i = 0; i < SUB - 1; i += 2) {
                s0 += tp[i * LN];
                s1 += tp[(i + 1) * LN];
            }
            s0 += tp[(SUB - 1) * LN];
            span[j * LN + ln] = s0 + s1;
        }
    }
    __syncthreads();

    // ---- Init window sum from 12 spans: covers [tg0-150, tg0+150) ----
    float4 ws = zero;
    #pragma unroll
    for (int j = 0; j < WSPAN; ++j) ws += span[(ty + j) * LN + ln];

    const int lbase = HALF + ty * SUB;     // local row of first output
    const int tg0   = t0 + ty * SUB;       // global row of first output
    float4* __restrict__ op =
        out + ((size_t)b * T + tg0) * F4 + hoff + ln;

    if (cx > 0 && cx < NCH - 1) {
        // ---- Interior chunk: count == 300 always ----
        #pragma unroll 5
        for (int i = 0; i < SUB; ++i) {
            const int lr = lbase + i;
            float4 xv = tile[lr * LN + ln];
            op[(size_t)i * F4] = f4_fnms(xv, ws, INV_FULL);
            ws += tile[(lr + HALF) * LN + ln] - tile[(lr - HALF) * LN + ln];
        }
    } else {
        // ---- Edge chunk: clamped count; end-exclusive cap at T-1 ----
        // zero-padded ws == sum over [max(t-150,0), min(t+150,T)); the
        // reference window is [max(t-150,0), min(t+150,T-1)), so for
        // t >= T-HALF we must additionally drop x[T-1].
        float4 xl = zero;
        if (t0 + CB >= T) xl = tile[(T - 1 - gbase) * LN + ln];
        for (int i = 0; i < SUB; ++i) {
            const int lr = lbase + i;
            const int t  = tg0 + i;
            int s = t - HALF; if (s < 0) s = 0;
            int e = t + HALF; if (e > T - 1) e = T - 1;
            float inv = 1.0f / (float)(e - s);
            float4 wsc = ws;
            if (t >= T - HALF) wsc -= xl;
            float4 xv = tile[lr * LN + ln];
            op[(size_t)i * F4] = f4_fnms(xv, wsc, inv);
            ws += tile[(lr + HALF) * LN + ln] - tile[(lr - HALF) * LN + ln];
        }
    }
}

extern "C" void kernel_launch(void* const* d_in, const int* in_sizes, int n_in,
                              void* d_out, int out_size)
{
    const float4* x = (const float4*)d_in[0];
    float4* out = (float4*)d_out;

    static bool attr_set = false;
    if (!attr_set) {
        cudaFuncSetAttribute(slide_smem_kernel,
                             cudaFuncAttributeMaxDynamicSharedMemorySize,
                             SMEM_BYTES);
        attr_set = true;
    }

    dim3 blk(LN, NSUB);        // 400 threads
    dim3 grid(NCH, 32, 2);     // 16 chunks x 32 batches x 2 feature-halves
    slide_smem_kernel<<<grid, blk, SMEM_BYTES>>>(x, out);
}

// round 4
// speedup vs baseline: 5.0768x; 1.6744x over previous
#include <cuda_runtime.h>
#include <cstdint>

// SlideMean_Norm: out = x - clamped_sliding_mean(x, win=300) along T
// x: [32, 1, 16000, 80] float32
// window for t: [max(t-150,0), min(t+150, T-1)), count = e - s
//
// Persistent strip blocks with a 620-row smem ring, cp.async double-buffered
// prefetch, and an incremental span-sum ring for O(1) window re-init.

namespace {
constexpr int T     = 16000;
constexpr int F4    = 20;       // 80 floats = 20 float4 per full row
constexpr int HALF  = 150;
constexpr int LN    = 10;       // float4 lanes per half-row (160 B)
constexpr int SUB   = 10;       // output rows per thread per iter
constexpr int CB    = 160;      // rows per iteration
constexpr int NSUB  = CB / SUB; // 16
constexpr int NTHR  = LN * NSUB;          // 160 threads
constexpr int L     = 4000;               // strip length
constexpr int ITERS = L / CB;             // 25
constexpr int R     = 2 * CB + 2 * HALF;  // 620-row ring
constexpr int SR    = R / SUB;            // 62-span ring
constexpr int PRO   = CB + 2 * HALF;      // 460 prologue rows
constexpr int WSPAN = 2 * HALF / SUB;     // 30 spans per window
constexpr float INV_FULL = 1.0f / 300.0f;
constexpr int SMEM_BYTES = (R * LN + SR * LN) * (int)sizeof(float4); // ~106.6 KB
}

__device__ __forceinline__ float4 operator+(float4 a, float4 b) {
    return make_float4(a.x+b.x, a.y+b.y, a.z+b.z, a.w+b.w);
}
__device__ __forceinline__ float4 operator-(float4 a, float4 b) {
    return make_float4(a.x-b.x, a.y-b.y, a.z-b.z, a.w-b.w);
}
__device__ __forceinline__ void operator+=(float4& a, float4 b) { a = a + b; }
__device__ __forceinline__ void operator-=(float4& a, float4 b) { a = a - b; }
__device__ __forceinline__ float4 f4_fnms(float4 x, float4 ws, float inv) {
    return make_float4(fmaf(-ws.x, inv, x.x), fmaf(-ws.y, inv, x.y),
                       fmaf(-ws.z, inv, x.z), fmaf(-ws.w, inv, x.w));
}

__device__ __forceinline__ void cpa16(uint32_t dst, const float4* src, bool valid) {
    int sz = valid ? 16 : 0;   // src-size 0 => zero-fill
    asm volatile("cp.async.cg.shared.global [%0], [%1], 16, %2;\n"
                 :: "r"(dst), "l"(src), "r"(sz));
}
__device__ __forceinline__ void cpa_commit() {
    asm volatile("cp.async.commit_group;\n");
}
template <int N>
__device__ __forceinline__ void cpa_wait() {
    asm volatile("cp.async.wait_group %0;\n" :: "n"(N));
}

__global__ __launch_bounds__(NTHR, 2) void slide_ring_kernel(
    const float4* __restrict__ x, float4* __restrict__ out)
{
    extern __shared__ float4 smem[];
    float4* __restrict__ tile = smem;            // [R][LN]
    float4* __restrict__ span = smem + R * LN;   // [SR][LN]

    const int ln  = threadIdx.x;     // 0..9
    const int ty  = threadIdx.y;     // 0..15
    const int tid = ty * LN + ln;
    const int S0  = blockIdx.x * L;              // strip base
    const int b   = blockIdx.y;
    const int hoff = blockIdx.z * LN;
    const int gfirst = S0 - HALF;

    const float4* __restrict__ xb = x   + (size_t)b * T * F4 + hoff;
    float4*       __restrict__ ob = out + (size_t)b * T * F4 + hoff;

    const uint32_t tile_sa = (uint32_t)__cvta_generic_to_shared(tile);
    const float4 zero = make_float4(0.f, 0.f, 0.f, 0.f);

    // ---- async load of local rows [l0, l1) into ring ----
    auto load_rows = [&](int l0, int l1) {
        const int njobs = (l1 - l0) * LN;
        for (int j = tid; j < njobs; j += NTHR) {
            int l   = l0 + j / LN;
            int ln2 = j % LN;
            int g   = gfirst + l;
            bool v  = (g >= 0) & (g < T);
            int gc  = v ? g : 0;
            int ring = l % R;
            cpa16(tile_sa + (uint32_t)(ring * LN + ln2) * 16,
                  xb + (size_t)gc * F4 + ln2, v);
        }
    };

    // ---- build span sums for local rows [l0, l1), SUB-aligned ----
    auto build_spans = [&](int l0, int l1) {
        const int nsp = (l1 - l0) / SUB;
        for (int j = tid; j < nsp * LN; j += NTHR) {
            int m   = l0 / SUB + j / LN;
            int ln2 = j % LN;
            int rr  = (m * SUB) % R;       // spans never wrap inside (SUB | R)
            float4 s = zero;
            #pragma unroll
            for (int k = 0; k < SUB; ++k) s += tile[(rr + k) * LN + ln2];
            span[(m % SR) * LN + ln2] = s;
        }
    };

    // ---- prologue: rows [0,460) + prefetch [460,620) ----
    load_rows(0, PRO);       cpa_commit();
    load_rows(PRO, PRO + CB); cpa_commit();
    cpa_wait<1>();
    __syncthreads();
    build_spans(0, PRO);
    __syncthreads();

    for (int i = 0; i < ITERS; ++i) {
        // ---- compute outputs [u, u+CB), u = S0 + i*CB ----
        {
            const int tg0 = S0 + i * CB + ty * SUB;

            // window init from 30 spans
            int m = (i * NSUB + ty) % SR;
            float4 ws = zero;
            #pragma unroll
            for (int j = 0; j < WSPAN; ++j) {
                ws += span[m * LN + ln];
                if (++m == SR) m = 0;
            }

            int rc = (i * CB + ty * SUB + HALF) % R;   // local row of tg0
            int rl = rc + HALF; if (rl >= R) rl -= R;
            int rt = rc - HALF; if (rt < 0)  rt += R;

            float4* __restrict__ op = ob + (size_t)tg0 * F4 + ln;

            const bool lo = (tg0 < HALF);
            const bool hi = (tg0 >= T - HALF);
            if (!lo && !hi) {
                #pragma unroll
                for (int k = 0; k < SUB; ++k) {
                    float4 xv = tile[rc * LN + ln];
                    __stcs(op + (size_t)k * F4, f4_fnms(xv, ws, INV_FULL));
                    ws += tile[rl * LN + ln] - tile[rt * LN + ln];
                    if (++rc == R) rc = 0;
                    if (++rl == R) rl = 0;
                    if (++rt == R) rt = 0;
                }
            } else {
                float4 xl = zero;
                if (hi) xl = tile[((T - 1 - gfirst) % R) * LN + ln];
                #pragma unroll
                for (int k = 0; k < SUB; ++k) {
                    const int t = tg0 + k;
                    int s = t - HALF; if (s < 0) s = 0;
                    int e = t + HALF; if (e > T - 1) e = T - 1;
                    float inv = 1.0f / (float)(e - s);
                    float4 wsc = ws;
                    if (t >= T - HALF) wsc -= xl;
                    float4 xv = tile[rc * LN + ln];
                    __stcs(op + (size_t)k * F4, f4_fnms(xv, wsc, inv));
                    ws += tile[rl * LN + ln] - tile[rt * LN + ln];
                    if (++rc == R) rc = 0;
                    if (++rl == R) rl = 0;
                    if (++rt == R) rt = 0;
                }
            }
        }

        // ---- pipeline turn-over ----
        if (i + 1 < ITERS) {
            cpa_wait<0>();         // rows [PRO+i*CB, PRO+(i+1)*CB) arrived
            __syncthreads();       // also fences compute readers before reuse
            build_spans(PRO + i * CB, PRO + (i + 1) * CB);
            if (i + 2 < ITERS) {   // prefetch rows for iter i+2
                load_rows(R + i * CB, R + (i + 1) * CB);
                cpa_commit();
            }
            __syncthreads();
        }
    }
}

extern "C" void kernel_launch(void* const* d_in, const int* in_sizes, int n_in,
                              void* d_out, int out_size)
{
    const float4* x = (const float4*)d_in[0];
    float4* out = (float4*)d_out;

    static bool attr_set = false;
    if (!attr_set) {
        cudaFuncSetAttribute(slide_ring_kernel,
                             cudaFuncAttributeMaxDynamicSharedMemorySize,
                             SMEM_BYTES);
        attr_set = true;
    }

    dim3 blk(LN, NSUB);            // 160 threads
    dim3 grid(T / L, 32, 2);       // 4 strips x 32 batches x 2 halves = 256
    slide_ring_kernel<<<grid, blk, SMEM_BYTES>>>(x, out);
}

// round 5
// speedup vs baseline: 5.2282x; 1.0298x over previous
#include <cuda_runtime.h>
#include <cstdint>

// SlideMean_Norm: out = x - clamped_sliding_mean(x, win=300) along T
// x: [32, 1, 16000, 80] float32
// window for t: [max(t-150,0), min(t+150, T-1)), count = e - s
//
// Persistent strip blocks, 620-row smem ring, cp.async double-buffered
// prefetch, exclusive span-prefix ring (Hillis-Steele extended) for O(1)
// window init, wrap-free inner slide loop.

namespace {
constexpr int T     = 16000;
constexpr int F4    = 20;       // 80 floats = 20 float4 per full row
constexpr int HALF  = 150;
constexpr int LN    = 10;       // float4 lanes per half-row (160 B)
constexpr int SUB   = 10;       // output rows per thread per iter
constexpr int CB    = 160;      // rows per iteration
constexpr int NSUB  = CB / SUB; // 16
constexpr int NTHR  = LN * NSUB;          // 160 threads
constexpr int L     = 4000;               // strip length
constexpr int ITERS = L / CB;             // 25
constexpr int R     = 2 * CB + 2 * HALF;  // 620-row ring
constexpr int PRO   = CB + 2 * HALF;      // 460 prologue rows
constexpr int NSPAN_PRO = PRO / SUB;      // 46
constexpr int SPR   = 64;                 // SP ring (pow2), live range 63
constexpr float INV_FULL = 1.0f / 300.0f;
constexpr int SMEM_BYTES =
    (R * LN + SPR * LN + 2 * NSUB * LN) * (int)sizeof(float4); // ~111.9 KB
}

__device__ __forceinline__ float4 operator+(float4 a, float4 b) {
    return make_float4(a.x+b.x, a.y+b.y, a.z+b.z, a.w+b.w);
}
__device__ __forceinline__ float4 operator-(float4 a, float4 b) {
    return make_float4(a.x-b.x, a.y-b.y, a.z-b.z, a.w-b.w);
}
__device__ __forceinline__ void operator+=(float4& a, float4 b) { a = a + b; }
__device__ __forceinline__ void operator-=(float4& a, float4 b) { a = a - b; }
__device__ __forceinline__ float4 f4_fnms(float4 x, float4 ws, float inv) {
    return make_float4(fmaf(-ws.x, inv, x.x), fmaf(-ws.y, inv, x.y),
                       fmaf(-ws.z, inv, x.z), fmaf(-ws.w, inv, x.w));
}

__device__ __forceinline__ void cpa16(uint32_t dst, const float4* src, bool valid) {
    int sz = valid ? 16 : 0;   // src-size 0 => zero-fill
    asm volatile("cp.async.cg.shared.global [%0], [%1], 16, %2;\n"
                 :: "r"(dst), "l"(src), "r"(sz));
}
__device__ __forceinline__ void cpa_commit() {
    asm volatile("cp.async.commit_group;\n");
}
template <int N>
__device__ __forceinline__ void cpa_wait() {
    asm volatile("cp.async.wait_group %0;\n" :: "n"(N));
}

__global__ __launch_bounds__(NTHR, 2) void slide_ring_kernel(
    const float4* __restrict__ x, float4* __restrict__ out)
{
    extern __shared__ float4 smem[];
    float4* __restrict__ tile = smem;                   // [R][LN]
    float4* __restrict__ sp   = smem + R * LN;          // [SPR][LN] span prefix
    float4* __restrict__ scrA = sp + SPR * LN;          // [NSUB][LN]
    float4* __restrict__ scrB = scrA + NSUB * LN;       // [NSUB][LN]

    const int ln  = threadIdx.x;     // 0..9
    const int ty  = threadIdx.y;     // 0..15
    const int tid = ty * LN + ln;
    const int S0  = blockIdx.x * L;
    const int b   = blockIdx.y;
    const int hoff = blockIdx.z * LN;
    const int gfirst = S0 - HALF;

    const float4* __restrict__ xb = x   + (size_t)b * T * F4 + hoff;
    float4*       __restrict__ ob = out + (size_t)b * T * F4 + hoff;

    const uint32_t tile_sa = (uint32_t)__cvta_generic_to_shared(tile);
    const float4 zero = make_float4(0.f, 0.f, 0.f, 0.f);

    // ---- async load of local rows [l0, l0+nrows) into ring ----
    auto load_rows = [&](int l0, int nrows) {
        const int ring0 = l0 % R;
        for (int r = ty; r < nrows; r += NSUB) {
            int rg = ring0 + r; if (rg >= R) rg -= R;
            int g  = gfirst + l0 + r;
            bool v = (g >= 0) & (g < T);
            cpa16(tile_sa + (uint32_t)(rg * LN + ln) * 16,
                  xb + (size_t)(v ? g : 0) * F4 + ln, v);
        }
    };

    // ---- build nspans spans for rows [l0, ...), scan, append to SP ring.
    //      J = global span index of first new span (SP[J] must exist). ----
    auto extend_spans = [&](int l0, int nspans, int J) {
        float4 s = zero;
        if (ty < nspans) {
            int rb = (l0 % R) + ty * SUB; if (rb >= R) rb -= R;
            const float4* __restrict__ tp = tile + rb * LN + ln;
            #pragma unroll
            for (int k = 0; k < SUB; ++k) s += tp[k * LN];
        }
        // Hillis-Steele inclusive scan over ty (ping-pong scratch)
        scrA[ty * LN + ln] = s;
        __syncthreads();
        float4 base = sp[(J & (SPR - 1)) * LN + ln];
        if (ty >= 1) s += scrA[(ty - 1) * LN + ln];
        scrB[ty * LN + ln] = s;
        __syncthreads();
        if (ty >= 2) s += scrB[(ty - 2) * LN + ln];
        scrA[ty * LN + ln] = s;
        __syncthreads();
        if (ty >= 4) s += scrA[(ty - 4) * LN + ln];
        scrB[ty * LN + ln] = s;
        __syncthreads();
        if (ty >= 8) s += scrB[(ty - 8) * LN + ln];
        if (ty < nspans)
            sp[((J + 1 + ty) & (SPR - 1)) * LN + ln] = base + s;
        __syncthreads();
    };

    // ---- prologue ----
    load_rows(0, PRO);        cpa_commit();
    load_rows(PRO, CB);       cpa_commit();
    cpa_wait<1>();
    __syncthreads();
    if (tid < LN) sp[tid] = zero;     // SP[0] = 0
    __syncthreads();
    extend_spans(0,   NSUB, 0);       // spans  0..15 -> SP[1..16]
    extend_spans(160, NSUB, 16);      // spans 16..31 -> SP[17..32]
    extend_spans(320, NSPAN_PRO - 2 * NSUB, 32); // spans 32..45 -> SP[33..46]

    for (int i = 0; i < ITERS; ++i) {
        // ---- compute outputs [S0+i*CB, +CB) ----
        {
            const int tg0 = S0 + i * CB + ty * SUB;
            const int m0  = i * NSUB + ty;

            float4 ws = sp[((m0 + 2 * HALF / SUB) & (SPR - 1)) * LN + ln]
                      - sp[(m0 & (SPR - 1)) * LN + ln];

            int rc = (i * CB + ty * SUB + HALF) % R;     // multiple of 10
            int rl = rc + HALF; if (rl >= R) rl -= R;
            int rt = rc - HALF; if (rt < 0)  rt += R;
            // segments of 10 rows never wrap (bases are multiples of 10)
            const float4* __restrict__ pc = tile + rc * LN + ln;
            const float4* __restrict__ pl = tile + rl * LN + ln;
            const float4* __restrict__ pt = tile + rt * LN + ln;
            float4* __restrict__ op = ob + (size_t)tg0 * F4 + ln;

            const bool lo = (tg0 < HALF);
            const bool hi = (tg0 >= T - HALF);
            if (!lo && !hi) {
                #pragma unroll
                for (int k = 0; k < SUB; ++k) {
                    float4 xv = pc[k * LN];
                    __stcs(op + (size_t)k * F4, f4_fnms(xv, ws, INV_FULL));
                    ws += pl[k * LN] - pt[k * LN];
                }
            } else {
                float4 xl = zero;
                if (hi) xl = tile[((T - 1 - gfirst) % R) * LN + ln];
                #pragma unroll
                for (int k = 0; k < SUB; ++k) {
                    const int t = tg0 + k;
                    int s = t - HALF; if (s < 0) s = 0;
                    int e = t + HALF; if (e > T - 1) e = T - 1;
                    float inv = 1.0f / (float)(e - s);
                    float4 wsc = ws;
                    if (t >= T - HALF) wsc -= xl;
                    float4 xv = pc[k * LN];
                    __stcs(op + (size_t)k * F4, f4_fnms(xv, wsc, inv));
                    ws += pl[k * LN] - pt[k * LN];
                }
            }
        }

        // ---- pipeline turn-over ----
        if (i + 1 < ITERS) {
            cpa_wait<0>();        // group for iter i+1 arrived
            __syncthreads();      // all compute readers done before reuse
            extend_spans(PRO + i * CB, NSUB, NSPAN_PRO + i * NSUB);
            if (i + 2 < ITERS) {
                load_rows(PRO + (i + 1) * CB, CB);
                cpa_commit();
            }
        }
    }
}

extern "C" void kernel_launch(void* const* d_in, const int* in_sizes, int n_in,
                              void* d_out, int out_size)
{
    const float4* x = (const float4*)d_in[0];
    float4* out = (float4*)d_out;

    static bool attr_set = false;
    if (!attr_set) {
        cudaFuncSetAttribute(slide_ring_kernel,
                             cudaFuncAttributeMaxDynamicSharedMemorySize,
                             SMEM_BYTES);
        attr_set = true;
    }

    dim3 blk(LN, NSUB);            // 160 threads
    dim3 grid(T / L, 32, 2);       // 4 strips x 32 batches x 2 halves = 256
    slide_ring_kernel<<<grid, blk, SMEM_BYTES>>>(x, out);
}